// round 6
// baseline (speedup 1.0000x reference)
#include <cuda_runtime.h>
#include <stdint.h>

// HSTUBlockPreprocessor: jagged concat of [ctx1 | ctx2 | interleave(item, action)]
// per sample, plus merged lengths appended after the values.
// TMA (cp.async.bulk) version: 16-row tiles staged through smem;
// 16 x 2KB bulk loads in, one 32KB contiguous bulk store out.

#define HSTU_D 512
#define ROW_BYTES (HSTU_D * 4)                 // 2048
#define ROWS_PER_TILE 16
#define TILE_BYTES (ROWS_PER_TILE * ROW_BYTES) // 32768
#define THREADS 128

__device__ __forceinline__ int comp_off(const int* __restrict__ item_off,
                                        const int* __restrict__ ctx1_off,
                                        const int* __restrict__ ctx2_off,
                                        int b)
{
    return ctx1_off[b] + ctx2_off[b] + 2 * item_off[b];
}

__global__ void __launch_bounds__(THREADS)
hstu_gather_tma(const float* __restrict__ item,
                const float* __restrict__ action,
                const float* __restrict__ ctx1,
                const float* __restrict__ ctx2,
                const int* __restrict__ item_off,
                const int* __restrict__ ctx1_off,
                const int* __restrict__ ctx2_off,
                float* __restrict__ out,
                int B, int total_rows, int n_copy_blocks)
{
    __shared__ __align__(128) unsigned char buf[TILE_BYTES];
    __shared__ __align__(8) unsigned long long mbar;

    const int tid = threadIdx.x;

    // ---- tail block: write merged lengths ----
    if (blockIdx.x >= (unsigned)n_copy_blocks) {
        if (tid < B) {
            int len = (ctx1_off[tid + 1] - ctx1_off[tid])
                    + (ctx2_off[tid + 1] - ctx2_off[tid])
                    + 2 * (item_off[tid + 1] - item_off[tid]);
            out[(size_t)total_rows * HSTU_D + tid] = (float)len;
        }
        return;
    }

    const int row0 = blockIdx.x * ROWS_PER_TILE;
    const uint32_t mbar_addr = (uint32_t)__cvta_generic_to_shared(&mbar);
    const uint32_t buf_addr  = (uint32_t)__cvta_generic_to_shared(buf);

    if (tid == 0) {
        asm volatile("mbarrier.init.shared.b64 [%0], %1;"
                     :: "r"(mbar_addr), "r"(1) : "memory");
    }

    // ---- sample lookup: parallel count (B <= 128 = blockDim).
    //      Doubles as the post-mbarrier-init block barrier. ----
    int b;
    {
        int pred = (tid < B) ? (comp_off(item_off, ctx1_off, ctx2_off, tid) <= row0) : 0;
        b = __syncthreads_count(pred) - 1;
    }

    const int rows_here = min(ROWS_PER_TILE, total_rows - row0);
    const int tile_bytes = rows_here * ROW_BYTES;

    if (tid == 0) {
        asm volatile("mbarrier.arrive.expect_tx.shared.b64 _, [%0], %1;"
                     :: "r"(mbar_addr), "r"((uint32_t)tile_bytes) : "memory");
    }

    // ---- threads 0..rows_here-1 each issue one 2KB bulk load ----
    if (tid < rows_here) {
        const int row = row0 + tid;

        // Tile spans <= 2 samples (min segment length 259 >> 16): advance at most once.
        const int nb = (b + 1 < B) ? comp_off(item_off, ctx1_off, ctx2_off, b + 1)
                                   : 0x7fffffff;
        const int bb = (row >= nb) ? (b + 1) : b;

        const int i0  = item_off[bb];
        const int c1o = ctx1_off[bb];
        const int c2o = ctx2_off[bb];
        const int c1  = ctx1_off[bb + 1] - c1o;
        const int c2  = ctx2_off[bb + 1] - c2o;
        const int r   = row - (c1o + c2o + 2 * i0);

        const float* src;
        if (r < c1) {
            src = ctx1 + (size_t)(c1o + r) * HSTU_D;
        } else if (r < c1 + c2) {
            src = ctx2 + (size_t)(c2o + (r - c1)) * HSTU_D;
        } else {
            const int t = r - c1 - c2;            // position in interleaved segment
            const int i = i0 + (t >> 1);          // item/action row index
            src = ((t & 1) ? action : item) + (size_t)i * HSTU_D;
        }

        asm volatile(
            "cp.async.bulk.shared::cluster.global.mbarrier::complete_tx::bytes "
            "[%0], [%1], %2, [%3];"
            :: "r"(buf_addr + (uint32_t)tid * ROW_BYTES), "l"(src),
               "r"((uint32_t)ROW_BYTES), "r"(mbar_addr)
            : "memory");
    }

    // ---- wait for all tile bytes ----
    {
        asm volatile(
            "{\n\t"
            ".reg .pred P1;\n\t"
            "WAIT_%=:\n\t"
            "mbarrier.try_wait.parity.shared.b64 P1, [%0], %1;\n\t"
            "@P1 bra DONE_%=;\n\t"
            "bra WAIT_%=;\n\t"
            "DONE_%=:\n\t"
            "}"
            :: "r"(mbar_addr), "r"(0) : "memory");
    }

    // ---- one contiguous bulk store of the whole tile ----
    if (tid == 0) {
        asm volatile("fence.proxy.async.shared::cta;" ::: "memory");
        float* dst = out + (size_t)row0 * HSTU_D;
        asm volatile(
            "cp.async.bulk.global.shared::cta.bulk_group [%0], [%1], %2;"
            :: "l"(dst), "r"(buf_addr), "r"((uint32_t)tile_bytes) : "memory");
        asm volatile("cp.async.bulk.commit_group;" ::: "memory");
        asm volatile("cp.async.bulk.wait_group.read 0;" ::: "memory");
    }
}

extern "C" void kernel_launch(void* const* d_in, const int* in_sizes, int n_in,
                              void* d_out, int out_size)
{
    const float* item   = (const float*)d_in[0];
    const float* action = (const float*)d_in[1];
    const float* ctx1   = (const float*)d_in[2];
    const float* ctx2   = (const float*)d_in[3];
    const int* item_off = (const int*)d_in[4];
    const int* ctx1_off = (const int*)d_in[5];
    const int* ctx2_off = (const int*)d_in[6];
    float* out = (float*)d_out;

    const int B = in_sizes[4] - 1;
    const long long total_vals = 2LL * in_sizes[0] + in_sizes[2] + in_sizes[3];
    const int total_rows = (int)(total_vals / HSTU_D);

    const int n_copy_blocks = (total_rows + ROWS_PER_TILE - 1) / ROWS_PER_TILE;
    const bool write_lengths = ((long long)out_size >= total_vals + B);
    const int grid = n_copy_blocks + (write_lengths ? 1 : 0);

    hstu_gather_tma<<<grid, THREADS>>>(item, action, ctx1, ctx2,
                                       item_off, ctx1_off, ctx2_off,
                                       out, B, total_rows, n_copy_blocks);
}